// round 13
// baseline (speedup 1.0000x reference)
#include <cuda_runtime.h>
#include <cuda_fp16.h>
#include <cstdint>

// ---------------- problem constants ----------------
#define K2     36864
#define MTOT   1024
#define NTOT   768
#define SPLITK 6
#define KS     (K2 / SPLITK)      // 6144 k per CTA
#define BM     128
#define BN     256
#define BK     64                 // fp16 k per pipeline stage (128B rows)
#define NIT    (KS / BK)          // 96

#define BATCH   64
#define T_IN    12
#define HORIZON 12

// ---------------- device scratch ----------------
__device__ float g_part[(size_t)SPLITK * MTOT * NTOT];    // [s][m][n]

// ---------------- SMEM layout ----------------
// per stage: A 16K | B 32K = 48K; 4 stages = 192K (both stored fp16)
#define OFF_A   0
#define OFF_B   16384
#define STAGE_BYTES 49152
#define SMEM_TOTAL (4 * STAGE_BYTES)   // 196608

// ---------------- helpers ----------------
static __device__ __forceinline__ void ldsm4(uint32_t (&r)[4], uint32_t addr) {
    asm volatile("ldmatrix.sync.aligned.m8n8.x4.shared.b16 {%0,%1,%2,%3}, [%4];"
                 : "=r"(r[0]), "=r"(r[1]), "=r"(r[2]), "=r"(r[3]) : "r"(addr));
}

static __device__ __forceinline__ void mma16816(float (&d)[4], const uint32_t (&a)[4],
                                                uint32_t b0, uint32_t b1) {
    asm volatile("mma.sync.aligned.m16n8k16.row.col.f32.f16.f16.f32 "
                 "{%0,%1,%2,%3}, {%4,%5,%6,%7}, {%8,%9}, {%0,%1,%2,%3};"
                 : "+f"(d[0]), "+f"(d[1]), "+f"(d[2]), "+f"(d[3])
                 : "r"(a[0]), "r"(a[1]), "r"(a[2]), "r"(a[3]), "r"(b0), "r"(b1));
}

static __device__ __forceinline__ uint32_t pack_h2(float lo, float hi) {
    uint32_t r;
    asm("cvt.rn.f16x2.f32 %0, %1, %2;" : "=r"(r) : "f"(hi), "f"(lo));
    return r;
}

// ---------------- A staging: 8 LDG.128 fp32 -> 4 STS.128 fp16 --------------
static __device__ __forceinline__ void loadA_regs(float4 (&av)[8],
                                                  const float* __restrict__ pA, int tid) {
    #pragma unroll
    for (int i = 0; i < 4; i++) {
        const int idx = i * 256 + tid;           // 0..1023 fp16 16B-chunks
        const int row = idx >> 3, c = idx & 7;
        const float* src = pA + (size_t)row * K2 + c * 8;
        av[2 * i]     = *reinterpret_cast<const float4*>(src);
        av[2 * i + 1] = *reinterpret_cast<const float4*>(src + 4);
    }
}
static __device__ __forceinline__ void storeA_smem(const float4 (&av)[8],
                                                   uint32_t stb, int tid) {
    #pragma unroll
    for (int i = 0; i < 4; i++) {
        const int idx = i * 256 + tid;
        const int row = idx >> 3, c = idx & 7;
        const uint32_t r0 = pack_h2(av[2 * i].x,     av[2 * i].y);
        const uint32_t r1 = pack_h2(av[2 * i].z,     av[2 * i].w);
        const uint32_t r2 = pack_h2(av[2 * i + 1].x, av[2 * i + 1].y);
        const uint32_t r3 = pack_h2(av[2 * i + 1].z, av[2 * i + 1].w);
        const uint32_t dst = stb + OFF_A + (uint32_t)(row * 128 + ((c ^ (row & 7)) << 4));
        asm volatile("st.shared.v4.b32 [%0], {%1,%2,%3,%4};"
                     :: "r"(dst), "r"(r0), "r"(r1), "r"(r2), "r"(r3));
    }
}

// ---------------- B staging: per half, 8 LDG.128 fp32 -> 4 STS.128 fp16 -----
// B fp16 stage = 2048 16B-chunks; half h covers chunks [h*1024, h*1024+1024).
static __device__ __forceinline__ void loadB_half(float4 (&bv)[8],
                                                  const float* __restrict__ pB,
                                                  int tid, int half) {
    #pragma unroll
    for (int i = 0; i < 4; i++) {
        const int rem = (half * 4 + i) * 256 + tid;   // chunk index 0..2047
        const int row = rem >> 3, c = rem & 7;
        const float* src = pB + (size_t)row * K2 + c * 8;
        bv[2 * i]     = *reinterpret_cast<const float4*>(src);
        bv[2 * i + 1] = *reinterpret_cast<const float4*>(src + 4);
    }
}
static __device__ __forceinline__ void stsB_half(const float4 (&bv)[8],
                                                 uint32_t stb, int tid, int half) {
    #pragma unroll
    for (int i = 0; i < 4; i++) {
        const int rem = (half * 4 + i) * 256 + tid;
        const int row = rem >> 3, c = rem & 7;
        const uint32_t r0 = pack_h2(bv[2 * i].x,     bv[2 * i].y);
        const uint32_t r1 = pack_h2(bv[2 * i].z,     bv[2 * i].w);
        const uint32_t r2 = pack_h2(bv[2 * i + 1].x, bv[2 * i + 1].y);
        const uint32_t r3 = pack_h2(bv[2 * i + 1].z, bv[2 * i + 1].w);
        const uint32_t dst = stb + OFF_B + (uint32_t)(row * 128 + ((c ^ (row & 7)) << 4));
        asm volatile("st.shared.v4.b32 [%0], {%1,%2,%3,%4};"
                     :: "r"(dst), "r"(r0), "r"(r1), "r"(r2), "r"(r3));
    }
}

// ---------------- kernel 1: split-K GEMM, BOTH operands converted in-kernel --
__global__ void __launch_bounds__(256, 1)
gemm_mma_kernel(const float* __restrict__ Afp32, const float* __restrict__ Bfp32)
{
    extern __shared__ char smem[];
    const uint32_t sb = (uint32_t)__cvta_generic_to_shared(smem);
    const int tid  = threadIdx.x;
    const int lane = tid & 31;
    const int wid  = tid >> 5;
    const int wm   = (wid >> 2) * 64;    // 2 row bands
    const int wn   = (wid & 3) * 64;     // 4 col bands
    const int bm = blockIdx.x, bn = blockIdx.y, s = blockIdx.z;

    const size_t kbase = (size_t)s * KS;
    const float* pA = Afp32 + (size_t)(bm * BM) * K2 + kbase;
    const float* pB = Bfp32 + (size_t)(bn * BN) * K2 + kbase;

    float acc[4][8][4];
    #pragma unroll
    for (int f = 0; f < 4; f++)
        #pragma unroll
        for (int j = 0; j < 8; j++)
            #pragma unroll
            for (int r = 0; r < 4; r++) acc[f][j][r] = 0.0f;

    // prologue: fill stages 0..2 (LDG fp32 -> cvt -> STS fp16 for A and B)
    #pragma unroll
    for (int j = 0; j < 3; j++) {
        const uint32_t stb = sb + (uint32_t)j * STAGE_BYTES;
        float4 v[8];
        loadA_regs(v, pA + j * BK, tid);      storeA_smem(v, stb, tid);
        loadB_half(v, pB + j * BK, tid, 0);   stsB_half(v, stb, tid, 0);
        loadB_half(v, pB + j * BK, tid, 1);   stsB_half(v, stb, tid, 1);
    }

    const int lr = lane & 15;     // ldmatrix row within 16
    const int lc = lane >> 4;     // ldmatrix k-half

    for (int it = 0; it < NIT; ++it) {
        const bool ld = (it + 3) < NIT;
        const float* pAs = pA + (size_t)(it + 3) * BK;
        const float* pBs = pB + (size_t)(it + 3) * BK;

        // stage it+3 staging, phase 1: A + B half0 LDGs in flight over compute
        float4 av[8], bv[8];
        if (ld) { loadA_regs(av, pAs, tid); loadB_half(bv, pBs, tid, 0); }

        __syncthreads();   // stage it fully written (STS from iter it-3 tail)

        const uint32_t stb = sb + (uint32_t)(it & 3) * STAGE_BYTES;
        const uint32_t wtb = sb + (uint32_t)((it + 3) & 3) * STAGE_BYTES;   // dead buffer

        #pragma unroll
        for (int kk = 0; kk < 2; kk++) {          // first half of compute
            const int c = kk * 2 + lc;
            uint32_t aH[4][4], bH[4][4];
            #pragma unroll
            for (int f = 0; f < 4; f++) {
                const int row = wm + f * 16 + lr;
                ldsm4(aH[f], stb + OFF_A + (uint32_t)(row * 128 + ((c ^ (row & 7)) << 4)));
            }
            #pragma unroll
            for (int g = 0; g < 4; g++) {
                const int row = wn + g * 16 + lr;
                ldsm4(bH[g], stb + OFF_B + (uint32_t)(row * 128 + ((c ^ (row & 7)) << 4)));
            }
            #pragma unroll
            for (int f = 0; f < 4; f++)
                #pragma unroll
                for (int j = 0; j < 8; j++)
                    mma16816(acc[f][j], aH[f], bH[j >> 1][j & 1], bH[j >> 1][(j & 1) + 2]);
        }

        // phase 2: retire B half0, reuse regs to fetch B half1
        if (ld) { stsB_half(bv, wtb, tid, 0); loadB_half(bv, pBs, tid, 1); }

        #pragma unroll
        for (int kk = 2; kk < 4; kk++) {          // second half of compute
            const int c = kk * 2 + lc;
            uint32_t aH[4][4], bH[4][4];
            #pragma unroll
            for (int f = 0; f < 4; f++) {
                const int row = wm + f * 16 + lr;
                ldsm4(aH[f], stb + OFF_A + (uint32_t)(row * 128 + ((c ^ (row & 7)) << 4)));
            }
            #pragma unroll
            for (int g = 0; g < 4; g++) {
                const int row = wn + g * 16 + lr;
                ldsm4(bH[g], stb + OFF_B + (uint32_t)(row * 128 + ((c ^ (row & 7)) << 4)));
            }
            #pragma unroll
            for (int f = 0; f < 4; f++)
                #pragma unroll
                for (int j = 0; j < 8; j++)
                    mma16816(acc[f][j], aH[f], bH[j >> 1][j & 1], bH[j >> 1][(j & 1) + 2]);
        }

        // tail: retire B half1 + A (no trailing barrier; next top barrier covers)
        if (ld) { stsB_half(bv, wtb, tid, 1); storeA_smem(av, wtb, tid); }
    }

    // store partials: [s][m][n]
    float* base = g_part + ((size_t)s * MTOT + (size_t)bm * BM) * NTOT + bn * BN;
    #pragma unroll
    for (int f = 0; f < 4; f++) {
        const int r0 = wm + f * 16 + (lane >> 2);
        #pragma unroll
        for (int j = 0; j < 8; j++) {
            const int n0 = wn + j * 8 + (lane & 3) * 2;
            *reinterpret_cast<float2*>(&base[(size_t)r0 * NTOT + n0]) =
                make_float2(acc[f][j][0], acc[f][j][1]);
            *reinterpret_cast<float2*>(&base[(size_t)(r0 + 8) * NTOT + n0]) =
                make_float2(acc[f][j][2], acc[f][j][3]);
        }
    }
}

// ---------------- kernel 2: split-K reduce + bias + einsum (b-fixed) --------
__global__ void __launch_bounds__(256)
epilogue_kernel(const float* __restrict__ x_all,   // output [64][12][1024][64]
                const float* __restrict__ b_hyp,   // [768]
                float* __restrict__ out)           // [64][12][1024]
{
    __shared__ float4 sh_h4[HORIZON * 17];   // [t][16] pad 17
    __shared__ float4 sh_x4[BATCH * 17];     // [b][16] pad 17

    const int n   = blockIdx.x;
    const int tid = threadIdx.x;

    // h: 192 float4 (768 floats): split-K reduce + bias
    if (tid < 192) {
        float4 a = reinterpret_cast<const float4*>(b_hyp)[tid];
        #pragma unroll
        for (int sp = 0; sp < SPLITK; sp++) {
            float4 v = *reinterpret_cast<const float4*>(
                &g_part[((size_t)sp * MTOT + n) * NTOT + tid * 4]);
            a.x += v.x; a.y += v.y; a.z += v.z; a.w += v.w;
        }
        sh_h4[(tid >> 4) * 17 + (tid & 15)] = a;
    }

    // x: 1024 float4 (64 b x 16 fc)
    #pragma unroll
    for (int r = 0; r < 4; r++) {
        const int i = tid + 256 * r;
        const int b = i >> 4, fc = i & 15;
        sh_x4[b * 17 + fc] = *reinterpret_cast<const float4*>(
            &x_all[((size_t)(b * T_IN + (T_IN - 1)) * MTOT + n) * 64 + fc * 4]);
    }
    __syncthreads();

    // thread fixes b, computes 3 horizons: xv loaded once per fc
    const int b  = tid & 63;
    const int tg = tid >> 6;       // 0..3 -> t = 3*tg + {0,1,2}
    float a0 = 0.f, a1 = 0.f, a2 = 0.f;
    #pragma unroll
    for (int fc = 0; fc < 16; fc++) {
        const float4 xv = sh_x4[b * 17 + fc];
        const float4 h0 = sh_h4[(3 * tg + 0) * 17 + fc];
        const float4 h1 = sh_h4[(3 * tg + 1) * 17 + fc];
        const float4 h2 = sh_h4[(3 * tg + 2) * 17 + fc];
        a0 += xv.x * h0.x + xv.y * h0.y + xv.z * h0.z + xv.w * h0.w;
        a1 += xv.x * h1.x + xv.y * h1.y + xv.z * h1.z + xv.w * h1.w;
        a2 += xv.x * h2.x + xv.y * h2.y + xv.z * h2.z + xv.w * h2.w;
    }
    out[((size_t)b * HORIZON + 3 * tg + 0) * MTOT + n] = a0;
    out[((size_t)b * HORIZON + 3 * tg + 1) * MTOT + n] = a1;
    out[((size_t)b * HORIZON + 3 * tg + 2) * MTOT + n] = a2;
}

// ---------------- launch ----------------
extern "C" void kernel_launch(void* const* d_in, const int* in_sizes, int n_in,
                              void* d_out, int out_size) {
    const float* output  = (const float*)d_in[0];   // [64,12,1024,64]
    const float* weights = (const float*)d_in[1];   // [1024,36864]
    const float* W_hyp   = (const float*)d_in[2];   // [768,36864]
    const float* b_hyp   = (const float*)d_in[3];   // [768]
    float* out = (float*)d_out;

    cudaFuncSetAttribute(gemm_mma_kernel,
                         cudaFuncAttributeMaxDynamicSharedMemorySize, SMEM_TOTAL);

    dim3 grid(MTOT / BM, NTOT / BN, SPLITK);   // (8, 3, 6) = 144 CTAs
    gemm_mma_kernel<<<grid, 256, SMEM_TOTAL>>>(weights, W_hyp);

    epilogue_kernel<<<MTOT, 256>>>(output, b_hyp, out);
}